// round 1
// baseline (speedup 1.0000x reference)
#include <cuda_runtime.h>

// Problem dims (fixed by the reference)
#define BB 4
#define SS 2048
#define DD 1024
#define HH 16
#define HD 64

// Scratch (allocation-free rule: __device__ globals)
__device__ float g_Q[(size_t)BB * HH * SS * HD];
__device__ float g_K[(size_t)BB * HH * SS * HD];
__device__ float g_V[(size_t)BB * HH * SS * HD];
__device__ float g_ctx[(size_t)BB * SS * DD];

// ---------------------------------------------------------------------------
// Kernel 1: QKV GEMM  (X[8192,1024] @ Wqkv[1024,3072] + bqkv), scatter to
// Q/K/V in [B,H,S,HD] layout. 128x128x8 tile, 256 threads, 8x8 per thread.
// ---------------------------------------------------------------------------
__global__ void __launch_bounds__(256) qkv_gemm(const float* __restrict__ X,
                                                const float* __restrict__ W,
                                                const float* __restrict__ bias) {
    __shared__ float As[8][128];
    __shared__ float Bs[8][128];
    const int tid  = threadIdx.x;
    const int m0   = blockIdx.y * 128;
    const int n0   = blockIdx.x * 128;
    const int arow = tid >> 1, acol = (tid & 1) << 2;
    const int brow = tid >> 5, bcol = (tid & 31) << 2;
    const int tx   = tid & 15, ty = tid >> 4;

    float acc[8][8];
#pragma unroll
    for (int i = 0; i < 8; i++)
#pragma unroll
        for (int j = 0; j < 8; j++) acc[i][j] = 0.f;

    const float* Ap = X + (size_t)(m0 + arow) * 1024 + acol;
    const float* Bp = W + (size_t)brow * 3072 + n0 + bcol;

    for (int k0 = 0; k0 < 1024; k0 += 8) {
        float4 a  = *(const float4*)(Ap + k0);
        float4 bv = *(const float4*)(Bp + (size_t)k0 * 3072);
        __syncthreads();
        As[acol + 0][arow] = a.x;
        As[acol + 1][arow] = a.y;
        As[acol + 2][arow] = a.z;
        As[acol + 3][arow] = a.w;
        *(float4*)&Bs[brow][bcol] = bv;
        __syncthreads();
#pragma unroll
        for (int kk = 0; kk < 8; kk++) {
            float ar[8], br[8];
            *(float4*)&ar[0] = *(const float4*)&As[kk][ty * 4];
            *(float4*)&ar[4] = *(const float4*)&As[kk][ty * 4 + 64];
            *(float4*)&br[0] = *(const float4*)&Bs[kk][tx * 4];
            *(float4*)&br[4] = *(const float4*)&Bs[kk][tx * 4 + 64];
#pragma unroll
            for (int i = 0; i < 8; i++)
#pragma unroll
                for (int j = 0; j < 8; j++) acc[i][j] += ar[i] * br[j];
        }
    }

#pragma unroll
    for (int i = 0; i < 8; i++) {
        int m  = m0 + ty * 4 + (i < 4 ? i : 60 + i);
        int bb = m >> 11, ss = m & 2047;
#pragma unroll
        for (int j = 0; j < 8; j++) {
            int   n   = n0 + tx * 4 + (j < 4 ? j : 60 + j);
            float v   = acc[i][j] + bias[n];
            int which = n >> 10;
            int rem   = n & 1023;
            int hh    = rem >> 6, hd = rem & 63;
            float* dst = (which == 0) ? g_Q : (which == 1 ? g_K : g_V);
            dst[(((size_t)bb * HH + hh) * SS + ss) * HD + hd] = v;
        }
    }
}

// ---------------------------------------------------------------------------
// Kernel 2: flash attention. Block = (b, h, 64-row q tile). 256 threads.
// Thread (ty,tx): rows ty*4+i, cols j*16+tx (conflict-free smem patterns).
// ---------------------------------------------------------------------------
#define LDK 65
#define LDP 68
#define ATTN_SMEM ((64 * 64 + 64 * LDK + 64 * 64 + 64 * LDP) * 4)

__global__ void __launch_bounds__(256) attn_kernel(const float* __restrict__ mask) {
    extern __shared__ float sm[];
    float* Qs = sm;                 // [64][64]
    float* Ks = Qs + 64 * 64;       // [64][LDK]
    float* Vs = Ks + 64 * LDK;      // [64][64]
    float* Ps = Vs + 64 * 64;       // [64][LDP]

    const int tid = threadIdx.x;
    const int tx  = tid & 15, ty = tid >> 4;
    const int b = blockIdx.z, h = blockIdx.y, qt = blockIdx.x;
    const size_t bh = (size_t)b * HH + h;

    const float* Qg = g_Q + (bh * SS + (size_t)qt * 64) * HD;
    const float* Kg = g_K + bh * SS * HD;
    const float* Vg = g_V + bh * SS * HD;

    // Load Q tile (layout matches gmem exactly)
    for (int i = tid; i < 1024; i += 256)
        ((float4*)Qs)[i] = ((const float4*)Qg)[i];

    float m_[4], l_[4], o_[4][4];
#pragma unroll
    for (int i = 0; i < 4; i++) {
        m_[i] = -1e30f;
        l_[i] = 0.f;
#pragma unroll
        for (int j = 0; j < 4; j++) o_[i][j] = 0.f;
    }

    const float scale = 0.125f;  // 1/sqrt(64)

    for (int kt = 0; kt < SS / 64; kt++) {
        __syncthreads();  // protect Ks/Vs/Ps from previous iteration readers
        // Load K (padded rows) and V tiles
        for (int i = tid; i < 1024; i += 256) {
            int    r = i >> 4;
            int    c = (i & 15) << 2;
            float4 k4 = ((const float4*)(Kg + (size_t)kt * 4096))[i];
            Ks[r * LDK + c + 0] = k4.x;
            Ks[r * LDK + c + 1] = k4.y;
            Ks[r * LDK + c + 2] = k4.z;
            Ks[r * LDK + c + 3] = k4.w;
            ((float4*)Vs)[i] = ((const float4*)(Vg + (size_t)kt * 4096))[i];
        }
        __syncthreads();

        // S = Q @ K^T
        float s_[4][4];
#pragma unroll
        for (int i = 0; i < 4; i++)
#pragma unroll
            for (int j = 0; j < 4; j++) s_[i][j] = 0.f;

#pragma unroll 4
        for (int kk = 0; kk < 64; kk += 4) {
            float4 q[4];
#pragma unroll
            for (int i = 0; i < 4; i++)
                q[i] = *(const float4*)&Qs[(ty * 4 + i) * 64 + kk];
#pragma unroll
            for (int j = 0; j < 4; j++) {
                const float* kp = &Ks[(j * 16 + tx) * LDK + kk];
                float k0 = kp[0], k1 = kp[1], k2 = kp[2], k3 = kp[3];
#pragma unroll
                for (int i = 0; i < 4; i++) {
                    s_[i][j] += q[i].x * k0;
                    s_[i][j] += q[i].y * k1;
                    s_[i][j] += q[i].z * k2;
                    s_[i][j] += q[i].w * k3;
                }
            }
        }

        // scale + mask
#pragma unroll
        for (int i = 0; i < 4; i++) {
            const float* mrow = mask + (size_t)(qt * 64 + ty * 4 + i) * SS + kt * 64;
#pragma unroll
            for (int j = 0; j < 4; j++)
                s_[i][j] = s_[i][j] * scale + mrow[j * 16 + tx];
        }

        // online softmax (row reductions across 16-lane half-warps)
#pragma unroll
        for (int i = 0; i < 4; i++) {
            float tm = s_[i][0];
#pragma unroll
            for (int j = 1; j < 4; j++) tm = fmaxf(tm, s_[i][j]);
#pragma unroll
            for (int off = 8; off >= 1; off >>= 1)
                tm = fmaxf(tm, __shfl_xor_sync(0xffffffffu, tm, off));
            float nm   = fmaxf(m_[i], tm);
            float corr = __expf(m_[i] - nm);
            float rs   = 0.f;
#pragma unroll
            for (int j = 0; j < 4; j++) {
                s_[i][j] = __expf(s_[i][j] - nm);
                rs += s_[i][j];
            }
#pragma unroll
            for (int off = 8; off >= 1; off >>= 1)
                rs += __shfl_xor_sync(0xffffffffu, rs, off);
            l_[i] = l_[i] * corr + rs;
            m_[i] = nm;
#pragma unroll
            for (int j = 0; j < 4; j++) o_[i][j] *= corr;
        }

        // stage P
#pragma unroll
        for (int i = 0; i < 4; i++)
#pragma unroll
            for (int j = 0; j < 4; j++)
                Ps[(ty * 4 + i) * LDP + j * 16 + tx] = s_[i][j];
        __syncthreads();

        // O += P @ V
#pragma unroll 4
        for (int c4 = 0; c4 < 64; c4 += 4) {
            float4 p[4];
#pragma unroll
            for (int i = 0; i < 4; i++)
                p[i] = *(const float4*)&Ps[(ty * 4 + i) * LDP + c4];
#pragma unroll
            for (int q = 0; q < 4; q++) {
                int c = c4 + q;
#pragma unroll
                for (int j = 0; j < 4; j++) {
                    float v = Vs[c * 64 + j * 16 + tx];
#pragma unroll
                    for (int i = 0; i < 4; i++) {
                        float pv = (q == 0) ? p[i].x : (q == 1) ? p[i].y
                                 : (q == 2) ? p[i].z : p[i].w;
                        o_[i][j] += pv * v;
                    }
                }
            }
        }
    }

    // epilogue: normalize and write to ctx in [B,S,D] layout
#pragma unroll
    for (int i = 0; i < 4; i++) {
        float inv = 1.f / l_[i];
        int   sg  = qt * 64 + ty * 4 + i;
#pragma unroll
        for (int j = 0; j < 4; j++)
            g_ctx[((size_t)b * SS + sg) * DD + h * HD + j * 16 + tx] = o_[i][j] * inv;
    }
}

// ---------------------------------------------------------------------------
// Kernel 3: output projection (ctx[8192,1024] @ Wout[1024,1024] + bout)
// ---------------------------------------------------------------------------
__global__ void __launch_bounds__(256) out_gemm(const float* __restrict__ W,
                                                const float* __restrict__ bias,
                                                float* __restrict__ out) {
    __shared__ float As[8][128];
    __shared__ float Bs[8][128];
    const int tid  = threadIdx.x;
    const int m0   = blockIdx.y * 128;
    const int n0   = blockIdx.x * 128;
    const int arow = tid >> 1, acol = (tid & 1) << 2;
    const int brow = tid >> 5, bcol = (tid & 31) << 2;
    const int tx   = tid & 15, ty = tid >> 4;

    float acc[8][8];
#pragma unroll
    for (int i = 0; i < 8; i++)
#pragma unroll
        for (int j = 0; j < 8; j++) acc[i][j] = 0.f;

    const float* Ap = g_ctx + (size_t)(m0 + arow) * 1024 + acol;
    const float* Bp = W + (size_t)brow * 1024 + n0 + bcol;

    for (int k0 = 0; k0 < 1024; k0 += 8) {
        float4 a  = *(const float4*)(Ap + k0);
        float4 bv = *(const float4*)(Bp + (size_t)k0 * 1024);
        __syncthreads();
        As[acol + 0][arow] = a.x;
        As[acol + 1][arow] = a.y;
        As[acol + 2][arow] = a.z;
        As[acol + 3][arow] = a.w;
        *(float4*)&Bs[brow][bcol] = bv;
        __syncthreads();
#pragma unroll
        for (int kk = 0; kk < 8; kk++) {
            float ar[8], br[8];
            *(float4*)&ar[0] = *(const float4*)&As[kk][ty * 4];
            *(float4*)&ar[4] = *(const float4*)&As[kk][ty * 4 + 64];
            *(float4*)&br[0] = *(const float4*)&Bs[kk][tx * 4];
            *(float4*)&br[4] = *(const float4*)&Bs[kk][tx * 4 + 64];
#pragma unroll
            for (int i = 0; i < 8; i++)
#pragma unroll
                for (int j = 0; j < 8; j++) acc[i][j] += ar[i] * br[j];
        }
    }

#pragma unroll
    for (int i = 0; i < 8; i++) {
        int m = m0 + ty * 4 + (i < 4 ? i : 60 + i);
#pragma unroll
        for (int j = 0; j < 8; j++) {
            int n = n0 + tx * 4 + (j < 4 ? j : 60 + j);
            out[(size_t)m * 1024 + n] = acc[i][j] + bias[n];
        }
    }
}

// ---------------------------------------------------------------------------
extern "C" void kernel_launch(void* const* d_in, const int* in_sizes, int n_in,
                              void* d_out, int out_size) {
    const float* x    = (const float*)d_in[0];
    const float* mask = (const float*)d_in[1];
    const float* Wqkv = (const float*)d_in[2];
    const float* bqkv = (const float*)d_in[3];
    const float* Wout = (const float*)d_in[4];
    const float* bout = (const float*)d_in[5];
    float*       out  = (float*)d_out;

    (void)in_sizes; (void)n_in; (void)out_size;

    // 1) QKV projection
    qkv_gemm<<<dim3(3072 / 128, 8192 / 128), 256>>>(x, Wqkv, bqkv);

    // 2) attention (dynamic smem > 48KB)
    cudaFuncSetAttribute(attn_kernel, cudaFuncAttributeMaxDynamicSharedMemorySize,
                         ATTN_SMEM);
    attn_kernel<<<dim3(SS / 64, HH, BB), 256, ATTN_SMEM>>>(mask);

    // 3) output projection
    out_gemm<<<dim3(1024 / 128, 8192 / 128), 256>>>(Wout, bout, out);
}

// round 2
// speedup vs baseline: 1.1056x; 1.1056x over previous
#include <cuda_runtime.h>

// Problem dims (fixed by the reference)
#define BB 4
#define SS 2048
#define DD 1024
#define HH 16
#define HD 64

typedef unsigned long long u64;

// ---- packed fp32x2 helpers (sm_103a FFMA2 path; ptxas never auto-fuses) ----
__device__ __forceinline__ u64 pk2(float lo, float hi) {
    u64 r;
    asm("mov.b64 %0, {%1, %2};"
        : "=l"(r) : "r"(__float_as_uint(lo)), "r"(__float_as_uint(hi)));
    return r;
}
__device__ __forceinline__ void fma2(u64& d, u64 a, u64 b) {
    asm("fma.rn.f32x2 %0, %1, %2, %0;" : "+l"(d) : "l"(a), "l"(b));
}
__device__ __forceinline__ void mul2(u64& d, u64 a) {
    asm("mul.rn.f32x2 %0, %0, %1;" : "+l"(d) : "l"(a));
}
__device__ __forceinline__ float2 up2(u64 v) {
    unsigned lo, hi;
    asm("mov.b64 {%0, %1}, %2;" : "=r"(lo), "=r"(hi) : "l"(v));
    return make_float2(__uint_as_float(lo), __uint_as_float(hi));
}

// Scratch (allocation-free rule: __device__ globals)
__device__ float g_Q[(size_t)BB * HH * SS * HD];
__device__ float g_K[(size_t)BB * HH * SS * HD];
__device__ float g_V[(size_t)BB * HH * SS * HD];
__device__ float g_ctx[(size_t)BB * SS * DD];

// ---------------------------------------------------------------------------
// Kernel 1: QKV GEMM (X[8192,1024] @ Wqkv[1024,3072] + bqkv) -> Q/K/V [B,H,S,HD]
// 128x128x8 tile, 256 threads, 8x8 per thread, fp32x2 packed FMA.
// ---------------------------------------------------------------------------
__global__ void __launch_bounds__(256) qkv_gemm(const float* __restrict__ X,
                                                const float* __restrict__ W,
                                                const float* __restrict__ bias) {
    __shared__ float As[8][128];
    __shared__ float Bs[8][128];
    const int tid  = threadIdx.x;
    const int m0   = blockIdx.y * 128;
    const int n0   = blockIdx.x * 128;
    const int arow = tid >> 1, acol = (tid & 1) << 2;
    const int brow = tid >> 5, bcol = (tid & 31) << 2;
    const int tx   = tid & 15, ty = tid >> 4;

    u64 acc2[8][4];
#pragma unroll
    for (int i = 0; i < 8; i++)
#pragma unroll
        for (int j = 0; j < 4; j++) acc2[i][j] = 0ull;

    const float* Ap = X + (size_t)(m0 + arow) * 1024 + acol;
    const float* Bp = W + (size_t)brow * 3072 + n0 + bcol;

    for (int k0 = 0; k0 < 1024; k0 += 8) {
        float4 a  = *(const float4*)(Ap + k0);
        float4 bv = *(const float4*)(Bp + (size_t)k0 * 3072);
        __syncthreads();
        As[acol + 0][arow] = a.x;
        As[acol + 1][arow] = a.y;
        As[acol + 2][arow] = a.z;
        As[acol + 3][arow] = a.w;
        *(float4*)&Bs[brow][bcol] = bv;
        __syncthreads();
#pragma unroll
        for (int kk = 0; kk < 8; kk++) {
            float ar[8], br[8];
            *(float4*)&ar[0] = *(const float4*)&As[kk][ty * 4];
            *(float4*)&ar[4] = *(const float4*)&As[kk][ty * 4 + 64];
            *(float4*)&br[0] = *(const float4*)&Bs[kk][tx * 4];
            *(float4*)&br[4] = *(const float4*)&Bs[kk][tx * 4 + 64];
            u64 bp[4];
#pragma unroll
            for (int jp = 0; jp < 4; jp++) bp[jp] = pk2(br[2 * jp], br[2 * jp + 1]);
#pragma unroll
            for (int i = 0; i < 8; i++) {
                u64 a2 = pk2(ar[i], ar[i]);
#pragma unroll
                for (int jp = 0; jp < 4; jp++) fma2(acc2[i][jp], a2, bp[jp]);
            }
        }
    }

#pragma unroll
    for (int i = 0; i < 8; i++) {
        int m  = m0 + ty * 4 + (i < 4 ? i : 60 + i);
        int bb = m >> 11, ss = m & 2047;
#pragma unroll
        for (int jp = 0; jp < 4; jp++) {
            float2 v2 = up2(acc2[i][jp]);
#pragma unroll
            for (int q = 0; q < 2; q++) {
                int   j   = 2 * jp + q;
                int   n   = n0 + tx * 4 + (j < 4 ? j : 60 + j);
                float v   = (q == 0 ? v2.x : v2.y) + bias[n];
                int which = n >> 10;
                int rem   = n & 1023;
                int hh    = rem >> 6, hd = rem & 63;
                float* dst = (which == 0) ? g_Q : (which == 1 ? g_K : g_V);
                dst[(((size_t)bb * HH + hh) * SS + ss) * HD + hd] = v;
            }
        }
    }
}

// ---------------------------------------------------------------------------
// Kernel 2: flash attention, fp32x2 packed. Block = (b, h, 64-row q tile).
// Q padded to 68, K rows padded to 66 (LDS.64 k-pairs), V transposed (66),
// P padded to 68. Thread (ty,tx): rows ty*4+i, cols j*16+tx.
// ---------------------------------------------------------------------------
#define LDQ 68
#define LDK 66
#define LDVT 66
#define LDP 68
#define ATTN_SMEM ((64 * LDQ + 64 * LDK + 64 * LDVT + 64 * LDP) * 4)

__global__ void __launch_bounds__(256) attn_kernel(const float* __restrict__ mask) {
    extern __shared__ float sm[];
    float* Qs  = sm;                  // [64][LDQ]
    float* Ks  = Qs + 64 * LDQ;       // [64][LDK]
    float* Vst = Ks + 64 * LDK;       // [64 cols][LDVT]  (transposed V)
    float* Ps  = Vst + 64 * LDVT;     // [64][LDP]

    const int tid = threadIdx.x;
    const int tx  = tid & 15, ty = tid >> 4;
    const int b = blockIdx.z, h = blockIdx.y, qt = blockIdx.x;
    const size_t bh = (size_t)b * HH + h;

    const float* Qg = g_Q + (bh * SS + (size_t)qt * 64) * HD;
    const float* Kg = g_K + bh * SS * HD;
    const float* Vg = g_V + bh * SS * HD;

    // Load Q tile into padded layout
    for (int i = tid; i < 1024; i += 256) {
        int r = i >> 4, c = (i & 15) << 2;
        *(float4*)&Qs[r * LDQ + c] = ((const float4*)Qg)[i];
    }

    float m_[4], l_[4];
    u64   o2[4][4];
#pragma unroll
    for (int i = 0; i < 4; i++) {
        m_[i] = -1e30f;
        l_[i] = 0.f;
#pragma unroll
        for (int j = 0; j < 4; j++) o2[i][j] = 0ull;
    }

    const float scale = 0.125f;  // 1/sqrt(64)

    for (int kt = 0; kt < SS / 64; kt++) {
        __syncthreads();  // protect Ks/Vst/Ps from previous iteration readers
        // Load K (row-padded) and V (transposed) tiles
        for (int i = tid; i < 1024; i += 256) {
            int    r  = i >> 4;
            int    c4 = (i & 15) << 2;
            float4 k4 = ((const float4*)(Kg + (size_t)kt * 4096))[i];
            Ks[r * LDK + c4 + 0] = k4.x;
            Ks[r * LDK + c4 + 1] = k4.y;
            Ks[r * LDK + c4 + 2] = k4.z;
            Ks[r * LDK + c4 + 3] = k4.w;
            float4 v4 = ((const float4*)(Vg + (size_t)kt * 4096))[i];
            Vst[(c4 + 0) * LDVT + r] = v4.x;
            Vst[(c4 + 1) * LDVT + r] = v4.y;
            Vst[(c4 + 2) * LDVT + r] = v4.z;
            Vst[(c4 + 3) * LDVT + r] = v4.w;
        }
        __syncthreads();

        // S = Q @ K^T  (pairs over k: both operands naturally contiguous)
        u64 s2[4][4];
#pragma unroll
        for (int i = 0; i < 4; i++)
#pragma unroll
            for (int j = 0; j < 4; j++) s2[i][j] = 0ull;

#pragma unroll 4
        for (int kk = 0; kk < 64; kk += 4) {
            u64 qa[4], qb[4];
#pragma unroll
            for (int i = 0; i < 4; i++) {
                float4 q = *(const float4*)&Qs[(ty * 4 + i) * LDQ + kk];
                qa[i] = pk2(q.x, q.y);
                qb[i] = pk2(q.z, q.w);
            }
#pragma unroll
            for (int j = 0; j < 4; j++) {
                const float* kp = &Ks[(j * 16 + tx) * LDK + kk];
                u64 k01 = *(const u64*)kp;
                u64 k23 = *(const u64*)(kp + 2);
#pragma unroll
                for (int i = 0; i < 4; i++) {
                    fma2(s2[i][j], qa[i], k01);
                    fma2(s2[i][j], qb[i], k23);
                }
            }
        }

        // fold pairs, scale + mask
        float s_[4][4];
#pragma unroll
        for (int i = 0; i < 4; i++) {
            const float* mrow = mask + (size_t)(qt * 64 + ty * 4 + i) * SS + kt * 64;
#pragma unroll
            for (int j = 0; j < 4; j++) {
                float2 v = up2(s2[i][j]);
                s_[i][j] = (v.x + v.y) * scale + mrow[j * 16 + tx];
            }
        }

        // online softmax (row reductions across 16-lane half-warps)
#pragma unroll
        for (int i = 0; i < 4; i++) {
            float tm = s_[i][0];
#pragma unroll
            for (int j = 1; j < 4; j++) tm = fmaxf(tm, s_[i][j]);
#pragma unroll
            for (int off = 8; off >= 1; off >>= 1)
                tm = fmaxf(tm, __shfl_xor_sync(0xffffffffu, tm, off));
            float nm   = fmaxf(m_[i], tm);
            float corr = __expf(m_[i] - nm);
            float rs   = 0.f;
#pragma unroll
            for (int j = 0; j < 4; j++) {
                s_[i][j] = __expf(s_[i][j] - nm);
                rs += s_[i][j];
            }
#pragma unroll
            for (int off = 8; off >= 1; off >>= 1)
                rs += __shfl_xor_sync(0xffffffffu, rs, off);
            l_[i] = l_[i] * corr + rs;
            m_[i] = nm;
            u64 c2 = pk2(corr, corr);
#pragma unroll
            for (int j = 0; j < 4; j++) mul2(o2[i][j], c2);
        }

        // stage P
#pragma unroll
        for (int i = 0; i < 4; i++)
#pragma unroll
            for (int j = 0; j < 4; j++)
                Ps[(ty * 4 + i) * LDP + j * 16 + tx] = s_[i][j];
        __syncthreads();

        // O += P @ V  (pairs over c; v-pairs contiguous via transposed V)
#pragma unroll 4
        for (int c4 = 0; c4 < 64; c4 += 4) {
            u64 pa[4], pb[4];
#pragma unroll
            for (int i = 0; i < 4; i++) {
                float4 p = *(const float4*)&Ps[(ty * 4 + i) * LDP + c4];
                pa[i] = pk2(p.x, p.y);
                pb[i] = pk2(p.z, p.w);
            }
#pragma unroll
            for (int j = 0; j < 4; j++) {
                const float* vp = &Vst[(j * 16 + tx) * LDVT + c4];
                u64 v01 = *(const u64*)vp;
                u64 v23 = *(const u64*)(vp + 2);
#pragma unroll
                for (int i = 0; i < 4; i++) {
                    fma2(o2[i][j], pa[i], v01);
                    fma2(o2[i][j], pb[i], v23);
                }
            }
        }
    }

    // epilogue: fold pairs, normalize, write ctx in [B,S,D] layout
#pragma unroll
    for (int i = 0; i < 4; i++) {
        float inv = 1.f / l_[i];
        int   sg  = qt * 64 + ty * 4 + i;
#pragma unroll
        for (int j = 0; j < 4; j++) {
            float2 v = up2(o2[i][j]);
            g_ctx[((size_t)b * SS + sg) * DD + h * HD + j * 16 + tx] =
                (v.x + v.y) * inv;
        }
    }
}

// ---------------------------------------------------------------------------
// Kernel 3: output projection (ctx[8192,1024] @ Wout[1024,1024] + bout)
// ---------------------------------------------------------------------------
__global__ void __launch_bounds__(256) out_gemm(const float* __restrict__ W,
                                                const float* __restrict__ bias,
                                                float* __restrict__ out) {
    __shared__ float As[8][128];
    __shared__ float Bs[8][128];
    const int tid  = threadIdx.x;
    const int m0   = blockIdx.y * 128;
    const int n0   = blockIdx.x * 128;
    const int arow = tid >> 1, acol = (tid & 1) << 2;
    const int brow = tid >> 5, bcol = (tid & 31) << 2;
    const int tx   = tid & 15, ty = tid >> 4;

    u64 acc2[8][4];
#pragma unroll
    for (int i = 0; i < 8; i++)
#pragma unroll
        for (int j = 0; j < 4; j++) acc2[i][j] = 0ull;

    const float* Ap = g_ctx + (size_t)(m0 + arow) * 1024 + acol;
    const float* Bp = W + (size_t)brow * 1024 + n0 + bcol;

    for (int k0 = 0; k0 < 1024; k0 += 8) {
        float4 a  = *(const float4*)(Ap + k0);
        float4 bv = *(const float4*)(Bp + (size_t)k0 * 1024);
        __syncthreads();
        As[acol + 0][arow] = a.x;
        As[acol + 1][arow] = a.y;
        As[acol + 2][arow] = a.z;
        As[acol + 3][arow] = a.w;
        *(float4*)&Bs[brow][bcol] = bv;
        __syncthreads();
#pragma unroll
        for (int kk = 0; kk < 8; kk++) {
            float ar[8], br[8];
            *(float4*)&ar[0] = *(const float4*)&As[kk][ty * 4];
            *(float4*)&ar[4] = *(const float4*)&As[kk][ty * 4 + 64];
            *(float4*)&br[0] = *(const float4*)&Bs[kk][tx * 4];
            *(float4*)&br[4] = *(const float4*)&Bs[kk][tx * 4 + 64];
            u64 bp[4];
#pragma unroll
            for (int jp = 0; jp < 4; jp++) bp[jp] = pk2(br[2 * jp], br[2 * jp + 1]);
#pragma unroll
            for (int i = 0; i < 8; i++) {
                u64 a2 = pk2(ar[i], ar[i]);
#pragma unroll
                for (int jp = 0; jp < 4; jp++) fma2(acc2[i][jp], a2, bp[jp]);
            }
        }
    }

#pragma unroll
    for (int i = 0; i < 8; i++) {
        int m = m0 + ty * 4 + (i < 4 ? i : 60 + i);
#pragma unroll
        for (int jp = 0; jp < 4; jp++) {
            float2 v2 = up2(acc2[i][jp]);
#pragma unroll
            for (int q = 0; q < 2; q++) {
                int j = 2 * jp + q;
                int n = n0 + tx * 4 + (j < 4 ? j : 60 + j);
                out[(size_t)m * 1024 + n] = (q == 0 ? v2.x : v2.y) + bias[n];
            }
        }
    }
}

// ---------------------------------------------------------------------------
extern "C" void kernel_launch(void* const* d_in, const int* in_sizes, int n_in,
                              void* d_out, int out_size) {
    const float* x    = (const float*)d_in[0];
    const float* mask = (const float*)d_in[1];
    const float* Wqkv = (const float*)d_in[2];
    const float* bqkv = (const float*)d_in[3];
    const float* Wout = (const float*)d_in[4];
    const float* bout = (const float*)d_in[5];
    float*       out  = (float*)d_out;

    (void)in_sizes; (void)n_in; (void)out_size;

    // 1) QKV projection
    qkv_gemm<<<dim3(3072 / 128, 8192 / 128), 256>>>(x, Wqkv, bqkv);

    // 2) attention (dynamic smem > 48KB)
    cudaFuncSetAttribute(attn_kernel, cudaFuncAttributeMaxDynamicSharedMemorySize,
                         ATTN_SMEM);
    attn_kernel<<<dim3(SS / 64, HH, BB), 256, ATTN_SMEM>>>(mask);

    // 3) output projection
    out_gemm<<<dim3(1024 / 128, 8192 / 128), 256>>>(Wout, bout, out);
}

// round 5
// speedup vs baseline: 1.2613x; 1.1408x over previous
#include <cuda_runtime.h>
#include <cuda_bf16.h>

// Problem dims (fixed by the reference)
#define BB 4
#define SS 2048
#define DD 1024
#define HH 16
#define HD 64

typedef unsigned long long u64;
typedef unsigned int u32;

// ---- packed fp32x2 helpers (attention kernel) ----
__device__ __forceinline__ u64 pk2(float lo, float hi) {
    u64 r;
    asm("mov.b64 %0, {%1, %2};"
        : "=l"(r) : "r"(__float_as_uint(lo)), "r"(__float_as_uint(hi)));
    return r;
}
__device__ __forceinline__ void fma2(u64& d, u64 a, u64 b) {
    asm("fma.rn.f32x2 %0, %1, %2, %0;" : "+l"(d) : "l"(a), "l"(b));
}
__device__ __forceinline__ void mul2(u64& d, u64 a) {
    asm("mul.rn.f32x2 %0, %0, %1;" : "+l"(d) : "l"(a));
}
__device__ __forceinline__ float2 up2(u64 v) {
    unsigned lo, hi;
    asm("mov.b64 {%0, %1}, %2;" : "=r"(lo), "=r"(hi) : "l"(v));
    return make_float2(__uint_as_float(lo), __uint_as_float(hi));
}

// ---- bf16 helpers ----
__device__ __forceinline__ u32 pkbf2(float a, float b) {
    __nv_bfloat162 t = __floats2bfloat162_rn(a, b);
    return *reinterpret_cast<u32*>(&t);
}
__device__ __forceinline__ float bf2f(unsigned short h) {
    __nv_bfloat16 t = *reinterpret_cast<__nv_bfloat16*>(&h);
    return __bfloat162float(t);
}
// split 2 floats -> hi u32 (2 bf16) and lo u32 (residual 2 bf16)
__device__ __forceinline__ void split2(float a, float b, u32& hi, u32& lo) {
    hi = pkbf2(a, b);
    float ra = a - bf2f((unsigned short)(hi & 0xffff));
    float rb = b - bf2f((unsigned short)(hi >> 16));
    lo = pkbf2(ra, rb);
}

// mma.sync m16n8k16 bf16 (plain sm_80+ feature; no 'a' gate)
__device__ __forceinline__ void mma16816(float* d, const u32* a, const u32* b) {
    asm volatile(
        "mma.sync.aligned.m16n8k16.row.col.f32.bf16.bf16.f32 "
        "{%0,%1,%2,%3}, {%4,%5,%6,%7}, {%8,%9}, {%0,%1,%2,%3};"
        : "+f"(d[0]), "+f"(d[1]), "+f"(d[2]), "+f"(d[3])
        : "r"(a[0]), "r"(a[1]), "r"(a[2]), "r"(a[3]), "r"(b[0]), "r"(b[1]));
}

// Scratch (allocation-free rule: __device__ globals)
__device__ float g_Q[(size_t)BB * HH * SS * HD];
__device__ float g_K[(size_t)BB * HH * SS * HD];
__device__ float g_V[(size_t)BB * HH * SS * HD];
__device__ float g_ctx[(size_t)BB * SS * DD];

// ---------------------------------------------------------------------------
// bf16x3 emulated-fp32 GEMM via mma.sync:
//   C[8192,NTOT] = A[8192,1024] @ W[1024,NTOT] + bias
// CTA tile 128x128, 8 warps (warp tile 64x32, grid 2m x 4n), K chunk 32.
// smem rows hold interleaved {hi,lo} u32 pairs, stride 40 words (conflict-free).
// MODE 0: scatter into Q/K/V. MODE 1: write to outp.
// ---------------------------------------------------------------------------
#define KW 40                 // u32 words per smem row
#define B2OFF (128 * 20)      // uint2 offset of B region

template <int NTOT, int MODE>
__global__ void __launch_bounds__(256) mm_bf16x3(const float* __restrict__ Ain,
                                                 const float* __restrict__ W,
                                                 const float* __restrict__ bias,
                                                 float* __restrict__ outp) {
    __shared__ u32 smw[2 * 128 * KW];  // A then B, 40KB
    uint2* A2 = (uint2*)smw;           // uint2 index = row*20 + kpair
    uint2* B2 = (uint2*)smw + B2OFF;

    const int tid  = threadIdx.x;
    const int wid  = tid >> 5, lane = tid & 31;
    const int wm   = wid & 1, wn = wid >> 1;  // warp grid 2 x 4
    const int m0   = blockIdx.y * 128;
    const int n0   = blockIdx.x * 128;
    const int lq   = lane >> 2;   // 0..7
    const int lr   = lane & 3;    // 0..3

    const float* A = (MODE == 1) ? g_ctx : Ain;

    // staging coords
    const int arow = tid >> 1, akb = (tid & 1) * 16;           // A: 128x32
    const int bkp  = tid & 15, bng = tid >> 4, bn0 = bng * 8;  // B: 16kp x 8n

    const float* aP = A + (size_t)(m0 + arow) * 1024 + akb;
    const float* wP = W + (size_t)(2 * bkp) * NTOT + n0 + bn0;

    float4 pa[4], pb[4];
#pragma unroll
    for (int q = 0; q < 4; q++) pa[q] = *(const float4*)(aP + q * 4);
    pb[0] = *(const float4*)(wP);
    pb[1] = *(const float4*)(wP + 4);
    pb[2] = *(const float4*)(wP + NTOT);
    pb[3] = *(const float4*)(wP + NTOT + 4);

    float d[4][4][4];  // mt (4 x m16) x nt (4 x n8) x frag
#pragma unroll
    for (int mt = 0; mt < 4; mt++)
#pragma unroll
        for (int nt = 0; nt < 4; nt++)
#pragma unroll
            for (int e = 0; e < 4; e++) d[mt][nt][e] = 0.f;

    for (int c = 0; c < 32; c++) {
        __syncthreads();
        // --- stage A: interleaved {hi,lo} ---
#pragma unroll
        for (int q = 0; q < 4; q++) {
            float4 v = pa[q];
            int kp = (akb >> 1) + q * 2;
            uint2 w0, w1;
            split2(v.x, v.y, w0.x, w0.y);
            split2(v.z, v.w, w1.x, w1.y);
            A2[arow * 20 + kp]     = w0;
            A2[arow * 20 + kp + 1] = w1;
        }
        // --- stage B transposed: Bs[n][kpair] = {hi,lo} of (W[2kp][n], W[2kp+1][n]) ---
        {
            float r0f[8], r1f[8];
            *(float4*)&r0f[0] = pb[0];
            *(float4*)&r0f[4] = pb[1];
            *(float4*)&r1f[0] = pb[2];
            *(float4*)&r1f[4] = pb[3];
#pragma unroll
            for (int n = 0; n < 8; n++) {
                uint2 w;
                split2(r0f[n], r1f[n], w.x, w.y);
                B2[(bn0 + n) * 20 + bkp] = w;
            }
        }
        // prefetch next chunk
        if (c < 31) {
#pragma unroll
            for (int q = 0; q < 4; q++)
                pa[q] = *(const float4*)(aP + (c + 1) * 32 + q * 4);
            const float* wn_ = wP + (size_t)(c + 1) * 32 * NTOT;
            pb[0] = *(const float4*)(wn_);
            pb[1] = *(const float4*)(wn_ + 4);
            pb[2] = *(const float4*)(wn_ + NTOT);
            pb[3] = *(const float4*)(wn_ + NTOT + 4);
        }
        __syncthreads();

        // --- compute: 2 k16 steps ---
#pragma unroll
        for (int ks = 0; ks < 2; ks++) {
            // B fragments first (shared across all mt)
            u32 bh[4][2], bl[4][2];
#pragma unroll
            for (int nt = 0; nt < 4; nt++) {
                int nr   = wn * 32 + nt * 8 + lq;
                int base = nr * 20 + ks * 8 + lr;
                uint2 r0 = B2[base];
                uint2 r1 = B2[base + 4];
                bh[nt][0] = r0.x; bh[nt][1] = r1.x;
                bl[nt][0] = r0.y; bl[nt][1] = r1.y;
            }
#pragma unroll
            for (int mt = 0; mt < 4; mt++) {
                int row  = wm * 64 + mt * 16 + lq;
                int base = row * 20 + ks * 8 + lr;
                uint2 q0 = A2[base];
                uint2 q1 = A2[base + 160];      // row+8
                uint2 q2 = A2[base + 4];        // k+8
                uint2 q3 = A2[base + 164];
                u32 ah[4] = {q0.x, q1.x, q2.x, q3.x};
                u32 al[4] = {q0.y, q1.y, q2.y, q3.y};
#pragma unroll
                for (int nt = 0; nt < 4; nt++) {
                    mma16816(d[mt][nt], ah, bh[nt]);
                    mma16816(d[mt][nt], ah, bl[nt]);
                    mma16816(d[mt][nt], al, bh[nt]);
                }
            }
        }
    }

    // --- epilogue ---
#pragma unroll
    for (int mt = 0; mt < 4; mt++) {
#pragma unroll
        for (int nt = 0; nt < 4; nt++) {
            int m = m0 + wm * 64 + mt * 16 + lq;
            int n = n0 + wn * 32 + nt * 8 + lr * 2;
            float2 bv = *(const float2*)&bias[n];
            float2 o0 = make_float2(d[mt][nt][0] + bv.x, d[mt][nt][1] + bv.y);
            float2 o1 = make_float2(d[mt][nt][2] + bv.x, d[mt][nt][3] + bv.y);
            if (MODE == 0) {
                int bb = m >> 11, ssq = m & 2047;
                int which = n >> 10;
                int head  = (n & 1023) >> 6;
                int hd    = n & 63;
                float* dst = (which == 0) ? g_Q : (which == 1 ? g_K : g_V);
                size_t base = (((size_t)bb * HH + head) * SS + ssq) * HD + hd;
                *(float2*)&dst[base]            = o0;
                *(float2*)&dst[base + 8 * HD]   = o1;   // row m+8
            } else {
                *(float2*)&outp[(size_t)m * 1024 + n]       = o0;
                *(float2*)&outp[(size_t)(m + 8) * 1024 + n] = o1;
            }
        }
    }
}

// ---------------------------------------------------------------------------
// Kernel 2: flash attention, fp32x2 packed (unchanged — passing at R2).
// ---------------------------------------------------------------------------
#define LDQ 68
#define LDK 66
#define LDVT 66
#define LDP 68
#define ATTN_SMEM ((64 * LDQ + 64 * LDK + 64 * LDVT + 64 * LDP) * 4)

__global__ void __launch_bounds__(256) attn_kernel(const float* __restrict__ mask) {
    extern __shared__ float sm[];
    float* Qs  = sm;
    float* Ks  = Qs + 64 * LDQ;
    float* Vst = Ks + 64 * LDK;
    float* Ps  = Vst + 64 * LDVT;

    const int tid = threadIdx.x;
    const int tx  = tid & 15, ty = tid >> 4;
    const int b = blockIdx.z, h = blockIdx.y, qt = blockIdx.x;
    const size_t bh = (size_t)b * HH + h;

    const float* Qg = g_Q + (bh * SS + (size_t)qt * 64) * HD;
    const float* Kg = g_K + bh * SS * HD;
    const float* Vg = g_V + bh * SS * HD;

    for (int i = tid; i < 1024; i += 256) {
        int r = i >> 4, c = (i & 15) << 2;
        *(float4*)&Qs[r * LDQ + c] = ((const float4*)Qg)[i];
    }

    float m_[4], l_[4];
    u64   o2[4][4];
#pragma unroll
    for (int i = 0; i < 4; i++) {
        m_[i] = -1e30f;
        l_[i] = 0.f;
#pragma unroll
        for (int j = 0; j < 4; j++) o2[i][j] = 0ull;
    }

    const float scale = 0.125f;

    for (int kt = 0; kt < SS / 64; kt++) {
        __syncthreads();
        for (int i = tid; i < 1024; i += 256) {
            int    r  = i >> 4;
            int    c4 = (i & 15) << 2;
            float4 k4 = ((const float4*)(Kg + (size_t)kt * 4096))[i];
            Ks[r * LDK + c4 + 0] = k4.x;
            Ks[r * LDK + c4 + 1] = k4.y;
            Ks[r * LDK + c4 + 2] = k4.z;
            Ks[r * LDK + c4 + 3] = k4.w;
            float4 v4 = ((const float4*)(Vg + (size_t)kt * 4096))[i];
            Vst[(c4 + 0) * LDVT + r] = v4.x;
            Vst[(c4 + 1) * LDVT + r] = v4.y;
            Vst[(c4 + 2) * LDVT + r] = v4.z;
            Vst[(c4 + 3) * LDVT + r] = v4.w;
        }
        __syncthreads();

        u64 s2[4][4];
#pragma unroll
        for (int i = 0; i < 4; i++)
#pragma unroll
            for (int j = 0; j < 4; j++) s2[i][j] = 0ull;

#pragma unroll 4
        for (int kk = 0; kk < 64; kk += 4) {
            u64 qa[4], qb[4];
#pragma unroll
            for (int i = 0; i < 4; i++) {
                float4 q = *(const float4*)&Qs[(ty * 4 + i) * LDQ + kk];
                qa[i] = pk2(q.x, q.y);
                qb[i] = pk2(q.z, q.w);
            }
#pragma unroll
            for (int j = 0; j < 4; j++) {
                const float* kp = &Ks[(j * 16 + tx) * LDK + kk];
                u64 k01 = *(const u64*)kp;
                u64 k23 = *(const u64*)(kp + 2);
#pragma unroll
                for (int i = 0; i < 4; i++) {
                    fma2(s2[i][j], qa[i], k01);
                    fma2(s2[i][j], qb[i], k23);
                }
            }
        }

        float s_[4][4];
#pragma unroll
        for (int i = 0; i < 4; i++) {
            const float* mrow = mask + (size_t)(qt * 64 + ty * 4 + i) * SS + kt * 64;
#pragma unroll
            for (int j = 0; j < 4; j++) {
                float2 v = up2(s2[i][j]);
                s_[i][j] = (v.x + v.y) * scale + mrow[j * 16 + tx];
            }
        }

#pragma unroll
        for (int i = 0; i < 4; i++) {
            float tm = s_[i][0];
#pragma unroll
            for (int j = 1; j < 4; j++) tm = fmaxf(tm, s_[i][j]);
#pragma unroll
            for (int off = 8; off >= 1; off >>= 1)
                tm = fmaxf(tm, __shfl_xor_sync(0xffffffffu, tm, off));
            float nm   = fmaxf(m_[i], tm);
            float corr = __expf(m_[i] - nm);
            float rs   = 0.f;
#pragma unroll
            for (int j = 0; j < 4; j++) {
                s_[i][j] = __expf(s_[i][j] - nm);
                rs += s_[i][j];
            }
#pragma unroll
            for (int off = 8; off >= 1; off >>= 1)
                rs += __shfl_xor_sync(0xffffffffu, rs, off);
            l_[i] = l_[i] * corr + rs;
            m_[i] = nm;
            u64 c2 = pk2(corr, corr);
#pragma unroll
            for (int j = 0; j < 4; j++) mul2(o2[i][j], c2);
        }

#pragma unroll
        for (int i = 0; i < 4; i++)
#pragma unroll
            for (int j = 0; j < 4; j++)
                Ps[(ty * 4 + i) * LDP + j * 16 + tx] = s_[i][j];
        __syncthreads();

#pragma unroll 4
        for (int c4 = 0; c4 < 64; c4 += 4) {
            u64 pa[4], pb[4];
#pragma unroll
            for (int i = 0; i < 4; i++) {
                float4 p = *(const float4*)&Ps[(ty * 4 + i) * LDP + c4];
                pa[i] = pk2(p.x, p.y);
                pb[i] = pk2(p.z, p.w);
            }
#pragma unroll
            for (int j = 0; j < 4; j++) {
                const float* vp = &Vst[(j * 16 + tx) * LDVT + c4];
                u64 v01 = *(const u64*)vp;
                u64 v23 = *(const u64*)(vp + 2);
#pragma unroll
                for (int i = 0; i < 4; i++) {
                    fma2(o2[i][j], pa[i], v01);
                    fma2(o2[i][j], pb[i], v23);
                }
            }
        }
    }

#pragma unroll
    for (int i = 0; i < 4; i++) {
        float inv = 1.f / l_[i];
        int   sg  = qt * 64 + ty * 4 + i;
#pragma unroll
        for (int j = 0; j < 4; j++) {
            float2 v = up2(o2[i][j]);
            g_ctx[((size_t)b * SS + sg) * DD + h * HD + j * 16 + tx] =
                (v.x + v.y) * inv;
        }
    }
}

// ---------------------------------------------------------------------------
extern "C" void kernel_launch(void* const* d_in, const int* in_sizes, int n_in,
                              void* d_out, int out_size) {
    const float* x    = (const float*)d_in[0];
    const float* mask = (const float*)d_in[1];
    const float* Wqkv = (const float*)d_in[2];
    const float* bqkv = (const float*)d_in[3];
    const float* Wout = (const float*)d_in[4];
    const float* bout = (const float*)d_in[5];
    float*       out  = (float*)d_out;

    (void)in_sizes; (void)n_in; (void)out_size;

    cudaFuncSetAttribute(attn_kernel,
                         cudaFuncAttributeMaxDynamicSharedMemorySize, ATTN_SMEM);

    // 1) QKV projection (mma.sync bf16x3)
    mm_bf16x3<3072, 0><<<dim3(3072 / 128, 8192 / 128), 256>>>(
        x, Wqkv, bqkv, nullptr);

    // 2) attention
    attn_kernel<<<dim3(SS / 64, HH, BB), 256, ATTN_SMEM>>>(mask);

    // 3) output projection (mma.sync bf16x3)
    mm_bf16x3<1024, 1><<<dim3(1024 / 128, 8192 / 128), 256>>>(
        x, Wout, bout, out);
}

// round 6
// speedup vs baseline: 1.9139x; 1.5174x over previous
#include <cuda_runtime.h>
#include <cuda_bf16.h>

// Problem dims (fixed by the reference)
#define BB 4
#define SS 2048
#define DD 1024
#define HH 16
#define HD 64

typedef unsigned long long u64;
typedef unsigned int u32;

// ---- bf16 helpers ----
__device__ __forceinline__ u32 pkbf2(float a, float b) {
    __nv_bfloat162 t = __floats2bfloat162_rn(a, b);
    return *reinterpret_cast<u32*>(&t);
}
__device__ __forceinline__ float bf2f(unsigned short h) {
    __nv_bfloat16 t = *reinterpret_cast<__nv_bfloat16*>(&h);
    return __bfloat162float(t);
}
// split 2 floats -> hi u32 (2 bf16) and lo u32 (residual 2 bf16)
__device__ __forceinline__ void split2(float a, float b, u32& hi, u32& lo) {
    hi = pkbf2(a, b);
    float ra = a - bf2f((unsigned short)(hi & 0xffff));
    float rb = b - bf2f((unsigned short)(hi >> 16));
    lo = pkbf2(ra, rb);
}

// mma.sync m16n8k16 bf16 (plain sm_80+ feature; no 'a' gate)
__device__ __forceinline__ void mma16816(float* d, const u32* a, const u32* b) {
    asm volatile(
        "mma.sync.aligned.m16n8k16.row.col.f32.bf16.bf16.f32 "
        "{%0,%1,%2,%3}, {%4,%5,%6,%7}, {%8,%9}, {%0,%1,%2,%3};"
        : "+f"(d[0]), "+f"(d[1]), "+f"(d[2]), "+f"(d[3])
        : "r"(a[0]), "r"(a[1]), "r"(a[2]), "r"(a[3]), "r"(b[0]), "r"(b[1]));
}

// Scratch (allocation-free rule: __device__ globals)
__device__ float g_Q[(size_t)BB * HH * SS * HD];
__device__ float g_K[(size_t)BB * HH * SS * HD];
__device__ float g_V[(size_t)BB * HH * SS * HD];
__device__ float g_ctx[(size_t)BB * SS * DD];

// ---------------------------------------------------------------------------
// bf16x3 emulated-fp32 GEMM via mma.sync (proven R5 version):
//   C[8192,NTOT] = A[8192,1024] @ W[1024,NTOT] + bias
// ---------------------------------------------------------------------------
#define KW 40
#define B2OFF (128 * 20)

template <int NTOT, int MODE>
__global__ void __launch_bounds__(256) mm_bf16x3(const float* __restrict__ Ain,
                                                 const float* __restrict__ W,
                                                 const float* __restrict__ bias,
                                                 float* __restrict__ outp) {
    __shared__ u32 smw[2 * 128 * KW];
    uint2* A2 = (uint2*)smw;
    uint2* B2 = (uint2*)smw + B2OFF;

    const int tid  = threadIdx.x;
    const int wid  = tid >> 5, lane = tid & 31;
    const int wm   = wid & 1, wn = wid >> 1;
    const int m0   = blockIdx.y * 128;
    const int n0   = blockIdx.x * 128;
    const int lq   = lane >> 2;
    const int lr   = lane & 3;

    const float* A = (MODE == 1) ? g_ctx : Ain;

    const int arow = tid >> 1, akb = (tid & 1) * 16;
    const int bkp  = tid & 15, bng = tid >> 4, bn0 = bng * 8;

    const float* aP = A + (size_t)(m0 + arow) * 1024 + akb;
    const float* wP = W + (size_t)(2 * bkp) * NTOT + n0 + bn0;

    float4 pa[4], pb[4];
#pragma unroll
    for (int q = 0; q < 4; q++) pa[q] = *(const float4*)(aP + q * 4);
    pb[0] = *(const float4*)(wP);
    pb[1] = *(const float4*)(wP + 4);
    pb[2] = *(const float4*)(wP + NTOT);
    pb[3] = *(const float4*)(wP + NTOT + 4);

    float d[4][4][4];
#pragma unroll
    for (int mt = 0; mt < 4; mt++)
#pragma unroll
        for (int nt = 0; nt < 4; nt++)
#pragma unroll
            for (int e = 0; e < 4; e++) d[mt][nt][e] = 0.f;

    for (int c = 0; c < 32; c++) {
        __syncthreads();
#pragma unroll
        for (int q = 0; q < 4; q++) {
            float4 v = pa[q];
            int kp = (akb >> 1) + q * 2;
            uint2 w0, w1;
            split2(v.x, v.y, w0.x, w0.y);
            split2(v.z, v.w, w1.x, w1.y);
            A2[arow * 20 + kp]     = w0;
            A2[arow * 20 + kp + 1] = w1;
        }
        {
            float r0f[8], r1f[8];
            *(float4*)&r0f[0] = pb[0];
            *(float4*)&r0f[4] = pb[1];
            *(float4*)&r1f[0] = pb[2];
            *(float4*)&r1f[4] = pb[3];
#pragma unroll
            for (int n = 0; n < 8; n++) {
                uint2 w;
                split2(r0f[n], r1f[n], w.x, w.y);
                B2[(bn0 + n) * 20 + bkp] = w;
            }
        }
        if (c < 31) {
#pragma unroll
            for (int q = 0; q < 4; q++)
                pa[q] = *(const float4*)(aP + (c + 1) * 32 + q * 4);
            const float* wn_ = wP + (size_t)(c + 1) * 32 * NTOT;
            pb[0] = *(const float4*)(wn_);
            pb[1] = *(const float4*)(wn_ + 4);
            pb[2] = *(const float4*)(wn_ + NTOT);
            pb[3] = *(const float4*)(wn_ + NTOT + 4);
        }
        __syncthreads();

#pragma unroll
        for (int ks = 0; ks < 2; ks++) {
            u32 bh[4][2], bl[4][2];
#pragma unroll
            for (int nt = 0; nt < 4; nt++) {
                int nr   = wn * 32 + nt * 8 + lq;
                int base = nr * 20 + ks * 8 + lr;
                uint2 r0 = B2[base];
                uint2 r1 = B2[base + 4];
                bh[nt][0] = r0.x; bh[nt][1] = r1.x;
                bl[nt][0] = r0.y; bl[nt][1] = r1.y;
            }
#pragma unroll
            for (int mt = 0; mt < 4; mt++) {
                int row  = wm * 64 + mt * 16 + lq;
                int base = row * 20 + ks * 8 + lr;
                uint2 q0 = A2[base];
                uint2 q1 = A2[base + 160];
                uint2 q2 = A2[base + 4];
                uint2 q3 = A2[base + 164];
                u32 ah[4] = {q0.x, q1.x, q2.x, q3.x};
                u32 al[4] = {q0.y, q1.y, q2.y, q3.y};
#pragma unroll
                for (int nt = 0; nt < 4; nt++) {
                    mma16816(d[mt][nt], ah, bh[nt]);
                    mma16816(d[mt][nt], ah, bl[nt]);
                    mma16816(d[mt][nt], al, bh[nt]);
                }
            }
        }
    }

#pragma unroll
    for (int mt = 0; mt < 4; mt++) {
#pragma unroll
        for (int nt = 0; nt < 4; nt++) {
            int m = m0 + wm * 64 + mt * 16 + lq;
            int n = n0 + wn * 32 + nt * 8 + lr * 2;
            float2 bv = *(const float2*)&bias[n];
            float2 o0 = make_float2(d[mt][nt][0] + bv.x, d[mt][nt][1] + bv.y);
            float2 o1 = make_float2(d[mt][nt][2] + bv.x, d[mt][nt][3] + bv.y);
            if (MODE == 0) {
                int bb = m >> 11, ssq = m & 2047;
                int which = n >> 10;
                int head  = (n & 1023) >> 6;
                int hd    = n & 63;
                float* dst = (which == 0) ? g_Q : (which == 1 ? g_K : g_V);
                size_t base = (((size_t)bb * HH + head) * SS + ssq) * HD + hd;
                *(float2*)&dst[base]          = o0;
                *(float2*)&dst[base + 8 * HD] = o1;
            } else {
                *(float2*)&outp[(size_t)m * 1024 + n]       = o0;
                *(float2*)&outp[(size_t)(m + 8) * 1024 + n] = o1;
            }
        }
    }
}

// ---------------------------------------------------------------------------
// Flash attention via mma.sync bf16x3. CTA = 128 q-rows, 8 warps (m16 each),
// key tile 64. Q frags register-resident; V transposed in smem; P repacked
// in registers (C-frag -> A-frag identity). Stride-36 padded smem rows.
// ---------------------------------------------------------------------------
#define AKW 36

__global__ void __launch_bounds__(256) attn_mma(const float* __restrict__ mask) {
    __shared__ u32 sm4[4 * 64 * AKW];  // 36864 B
    u32* Ksh = sm4;
    u32* Ksl = sm4 + 64 * AKW;
    u32* Vth = sm4 + 2 * 64 * AKW;
    u32* Vtl = sm4 + 3 * 64 * AKW;
    // Q staging overlays the whole buffer (used only before the main loop)
    u32* Qsh = sm4;
    u32* Qsl = sm4 + 128 * AKW;

    const int tid  = threadIdx.x;
    const int wid  = tid >> 5, lane = tid & 31;
    const int lq   = lane >> 2, lr = lane & 3;
    const int qt = blockIdx.x, h = blockIdx.y, b = blockIdx.z;
    const size_t bh = (size_t)b * HH + h;
    const int q0 = qt * 128;
    const int qw = q0 + wid * 16;

    const float* Qg = g_Q + (bh * SS + q0) * HD;
    const float* Kg = g_K + bh * SS * HD;
    const float* Vg = g_V + bh * SS * HD;

    // ---- stage Q (hi/lo bf16 pairs) ----
    {
        int row = tid >> 1;
        int pb  = (tid & 1) * 16;  // u32 pair base
        const float* qp = Qg + row * 64 + pb * 2;
        u32* dh = Qsh + row * AKW + pb;
        u32* dl = Qsl + row * AKW + pb;
#pragma unroll
        for (int q = 0; q < 8; q++) {
            float4 v = ((const float4*)qp)[q];
            u32 h0, l0, h1, l1;
            split2(v.x, v.y, h0, l0);
            split2(v.z, v.w, h1, l1);
            dh[2 * q] = h0; dh[2 * q + 1] = h1;
            dl[2 * q] = l0; dl[2 * q + 1] = l1;
        }
    }
    __syncthreads();

    // ---- load Q a-frags (register-resident for whole loop) ----
    u32 qfh[4][4], qfl[4][4];
    {
        const int r0 = (wid * 16 + lq) * AKW;
        const int r1 = r0 + 8 * AKW;
#pragma unroll
        for (int kc = 0; kc < 4; kc++) {
            qfh[kc][0] = Qsh[r0 + 8 * kc + lr];
            qfh[kc][1] = Qsh[r1 + 8 * kc + lr];
            qfh[kc][2] = Qsh[r0 + 8 * kc + 4 + lr];
            qfh[kc][3] = Qsh[r1 + 8 * kc + 4 + lr];
            qfl[kc][0] = Qsl[r0 + 8 * kc + lr];
            qfl[kc][1] = Qsl[r1 + 8 * kc + lr];
            qfl[kc][2] = Qsl[r0 + 8 * kc + 4 + lr];
            qfl[kc][3] = Qsl[r1 + 8 * kc + 4 + lr];
        }
    }

    float o[8][4];
#pragma unroll
    for (int nt = 0; nt < 8; nt++)
#pragma unroll
        for (int e = 0; e < 4; e++) o[nt][e] = 0.f;
    float m0r = -1e30f, m1r = -1e30f, l0r = 0.f, l1r = 0.f;

    const float scale = 0.125f;
    const float* mp0 = mask + (size_t)(qw + lq) * SS;
    const float* mp1 = mask + (size_t)(qw + lq + 8) * SS;

    for (int kt = 0; kt < SS / 64; kt++) {
        const int k0 = kt * 64;
        __syncthreads();  // protect smem from previous iteration readers

        // ---- stage K tile (row-major hd-pairs) ----
        {
            int row = tid >> 2;
            int cg  = tid & 3;
            const float* kp_ = Kg + (size_t)(k0 + row) * 64 + cg * 16;
            u32* dh = Ksh + row * AKW + cg * 8;
            u32* dl = Ksl + row * AKW + cg * 8;
#pragma unroll
            for (int q = 0; q < 4; q++) {
                float4 v = ((const float4*)kp_)[q];
                u32 h0, l0, h1, l1;
                split2(v.x, v.y, h0, l0);
                split2(v.z, v.w, h1, l1);
                dh[2 * q] = h0; dh[2 * q + 1] = h1;
                dl[2 * q] = l0; dl[2 * q + 1] = l1;
            }
        }
        // ---- stage V transposed (key-pairs along rows of hd) ----
        {
            int kp = lane;          // key pair 0..31
            int h0 = wid * 8;       // 8 hd per warp
            const float* va = Vg + (size_t)(k0 + 2 * kp) * 64 + h0;
            float a8[8], b8[8];
            *(float4*)&a8[0] = ((const float4*)va)[0];
            *(float4*)&a8[4] = ((const float4*)va)[1];
            *(float4*)&b8[0] = ((const float4*)(va + 64))[0];
            *(float4*)&b8[4] = ((const float4*)(va + 64))[1];
#pragma unroll
            for (int i = 0; i < 8; i++) {
                u32 hi, lo;
                split2(a8[i], b8[i], hi, lo);
                Vth[(h0 + i) * AKW + kp] = hi;
                Vtl[(h0 + i) * AKW + kp] = lo;
            }
        }
        __syncthreads();

        // ---- S = Q @ K^T (bf16x3) ----
        float s[8][4];
#pragma unroll
        for (int nt = 0; nt < 8; nt++)
#pragma unroll
            for (int e = 0; e < 4; e++) s[nt][e] = 0.f;

#pragma unroll
        for (int kc = 0; kc < 4; kc++) {
#pragma unroll
            for (int nt = 0; nt < 8; nt++) {
                int base = (nt * 8 + lq) * AKW + 8 * kc + lr;
                u32 bhf[2] = {Ksh[base], Ksh[base + 4]};
                u32 blf[2] = {Ksl[base], Ksl[base + 4]};
                mma16816(s[nt], qfh[kc], bhf);
                mma16816(s[nt], qfh[kc], blf);
                mma16816(s[nt], qfl[kc], bhf);
            }
        }

        // ---- scale + mask ----
#pragma unroll
        for (int nt = 0; nt < 8; nt++) {
            float2 ma = *(const float2*)(mp0 + k0 + nt * 8 + 2 * lr);
            float2 mb = *(const float2*)(mp1 + k0 + nt * 8 + 2 * lr);
            s[nt][0] = s[nt][0] * scale + ma.x;
            s[nt][1] = s[nt][1] * scale + ma.y;
            s[nt][2] = s[nt][2] * scale + mb.x;
            s[nt][3] = s[nt][3] * scale + mb.y;
        }

        // ---- online softmax (rows lq and lq+8) ----
        float r0 = -1e30f, r1 = -1e30f;
#pragma unroll
        for (int nt = 0; nt < 8; nt++) {
            r0 = fmaxf(r0, fmaxf(s[nt][0], s[nt][1]));
            r1 = fmaxf(r1, fmaxf(s[nt][2], s[nt][3]));
        }
        r0 = fmaxf(r0, __shfl_xor_sync(0xffffffffu, r0, 1));
        r0 = fmaxf(r0, __shfl_xor_sync(0xffffffffu, r0, 2));
        r1 = fmaxf(r1, __shfl_xor_sync(0xffffffffu, r1, 1));
        r1 = fmaxf(r1, __shfl_xor_sync(0xffffffffu, r1, 2));

        float nm0 = fmaxf(m0r, r0), nm1 = fmaxf(m1r, r1);
        float c0 = __expf(m0r - nm0), c1 = __expf(m1r - nm1);
        float sum0 = 0.f, sum1 = 0.f;
#pragma unroll
        for (int nt = 0; nt < 8; nt++) {
            s[nt][0] = __expf(s[nt][0] - nm0);
            s[nt][1] = __expf(s[nt][1] - nm0);
            s[nt][2] = __expf(s[nt][2] - nm1);
            s[nt][3] = __expf(s[nt][3] - nm1);
            sum0 += s[nt][0] + s[nt][1];
            sum1 += s[nt][2] + s[nt][3];
        }
        sum0 += __shfl_xor_sync(0xffffffffu, sum0, 1);
        sum0 += __shfl_xor_sync(0xffffffffu, sum0, 2);
        sum1 += __shfl_xor_sync(0xffffffffu, sum1, 1);
        sum1 += __shfl_xor_sync(0xffffffffu, sum1, 2);
        l0r = l0r * c0 + sum0;
        l1r = l1r * c1 + sum1;
        m0r = nm0; m1r = nm1;
#pragma unroll
        for (int nt = 0; nt < 8; nt++) {
            o[nt][0] *= c0; o[nt][1] *= c0;
            o[nt][2] *= c1; o[nt][3] *= c1;
        }

        // ---- O += P @ V (bf16x3); P repack = C-frag -> A-frag identity ----
#pragma unroll
        for (int kc = 0; kc < 4; kc++) {
            u32 ph[4], pl[4];
            split2(s[2 * kc][0], s[2 * kc][1], ph[0], pl[0]);
            split2(s[2 * kc][2], s[2 * kc][3], ph[1], pl[1]);
            split2(s[2 * kc + 1][0], s[2 * kc + 1][1], ph[2], pl[2]);
            split2(s[2 * kc + 1][2], s[2 * kc + 1][3], ph[3], pl[3]);
#pragma unroll
            for (int nt = 0; nt < 8; nt++) {
                int base = (nt * 8 + lq) * AKW + 8 * kc + lr;
                u32 bhf[2] = {Vth[base], Vth[base + 4]};
                u32 blf[2] = {Vtl[base], Vtl[base + 4]};
                mma16816(o[nt], ph, bhf);
                mma16816(o[nt], ph, blf);
                mma16816(o[nt], pl, bhf);
            }
        }
    }

    // ---- epilogue: normalize, write ctx [B,S,D] ----
    float inv0 = 1.f / l0r, inv1 = 1.f / l1r;
    float* c0p = g_ctx + ((size_t)b * SS + qw + lq) * DD + h * HD;
    float* c1p = c0p + 8 * DD;
#pragma unroll
    for (int nt = 0; nt < 8; nt++) {
        int col = nt * 8 + 2 * lr;
        *(float2*)(c0p + col) = make_float2(o[nt][0] * inv0, o[nt][1] * inv0);
        *(float2*)(c1p + col) = make_float2(o[nt][2] * inv1, o[nt][3] * inv1);
    }
}

// ---------------------------------------------------------------------------
extern "C" void kernel_launch(void* const* d_in, const int* in_sizes, int n_in,
                              void* d_out, int out_size) {
    const float* x    = (const float*)d_in[0];
    const float* mask = (const float*)d_in[1];
    const float* Wqkv = (const float*)d_in[2];
    const float* bqkv = (const float*)d_in[3];
    const float* Wout = (const float*)d_in[4];
    const float* bout = (const float*)d_in[5];
    float*       out  = (float*)d_out;

    (void)in_sizes; (void)n_in; (void)out_size;

    // 1) QKV projection (mma.sync bf16x3)
    mm_bf16x3<3072, 0><<<dim3(3072 / 128, 8192 / 128), 256>>>(
        x, Wqkv, bqkv, nullptr);

    // 2) attention (mma.sync bf16x3 flash)
    attn_mma<<<dim3(SS / 128, HH, BB), 256>>>(mask);

    // 3) output projection (mma.sync bf16x3)
    mm_bf16x3<1024, 1><<<dim3(1024 / 128, 8192 / 128), 256>>>(
        x, Wout, bout, out);
}